// round 5
// baseline (speedup 1.0000x reference)
#include <cuda_runtime.h>
#include <cstdint>

// LSTM: B=32, T=1024, I=512, H=512, gates G=4H=2048
// out layout: outs[B][T][H] (16777216 floats) | h_T[B][H] | c_T[B][H]

#define NB 32
#define NT 1024
#define NI 512
#define NH 512
#define NG 2048

#define GROUPS 4
#define GBLK 32            // blocks per group
#define GBATCH 8           // batches per group
#define SCAN_BLOCKS (GROUPS * GBLK)
#define SCAN_THREADS 512
#define WPAD 516           // padded row stride (floats); 516*4B = 2064B (16B-aligned, bank-shifted)

// ---------------- device scratch ----------------
__device__ float g_xg[(size_t)NT * NB * NG];            // [t][b][g]
__device__ float g_h[2][GROUPS][GBATCH][NH];            // double-buffered per-group hidden
__device__ unsigned g_bars[GROUPS * 32];                // one padded counter per group

// ---------------- f32x2 helpers ----------------
__device__ __forceinline__ unsigned long long pk2(float lo, float hi) {
    unsigned long long r;
    asm("mov.b64 %0, {%1, %2};" : "=l"(r) : "f"(lo), "f"(hi));
    return r;
}
__device__ __forceinline__ void fma2(unsigned long long& acc,
                                     unsigned long long a, unsigned long long b) {
    asm("fma.rn.f32x2 %0, %1, %2, %0;" : "+l"(acc) : "l"(a), "l"(b));
}
__device__ __forceinline__ float2 upk(unsigned long long v) {
    float2 f;
    asm("mov.b64 {%0, %1}, %2;" : "=f"(f.x), "=f"(f.y) : "l"(v));
    return f;
}
__device__ __forceinline__ float sigf(float x) {
    return 1.0f / (1.0f + __expf(-x));
}
__device__ __forceinline__ float tanhfast(float x) {
    return 1.0f - 2.0f / (__expf(2.0f * x) + 1.0f);
}

// ---------------- init (every replay) ----------------
__global__ void k_init() {
    int t = threadIdx.x + blockIdx.x * blockDim.x;
    int n = gridDim.x * blockDim.x;
    for (int i = t; i < GROUPS * 32; i += n) g_bars[i] = 0u;
    float* h = &g_h[0][0][0][0];
    for (int i = t; i < 2 * GROUPS * GBATCH * NH; i += n) h[i] = 0.0f;
}

// ---------------- GEMM: xg[t][b][g] = x . W_ih^T + b_ih + b_hh (unchanged) ----------------
__global__ void __launch_bounds__(256) k_gemm(const float* __restrict__ X,
                                              const float* __restrict__ Wih,
                                              const float* __restrict__ bih,
                                              const float* __restrict__ bhh) {
    __shared__ float As[2][16][132];
    __shared__ float Bs[2][16][132];

    const int tid = threadIdx.x;
    const int m0 = blockIdx.y * 128;
    const int n0 = blockIdx.x * 128;
    const int tx = tid & 15;
    const int ty = tid >> 4;
    const int lr = tid >> 2;
    const int lq = tid & 3;

    unsigned long long acc[8][4];
#pragma unroll
    for (int i = 0; i < 8; i++)
#pragma unroll
        for (int j = 0; j < 4; j++) acc[i][j] = 0ull;

    float4 aR[2], bR[2];
#pragma unroll
    for (int l = 0; l < 2; l++) {
        aR[l] = __ldg((const float4*)(X   + (size_t)(m0 + lr + 64 * l) * NI + 4 * lq));
        bR[l] = __ldg((const float4*)(Wih + (size_t)(n0 + lr + 64 * l) * NI + 4 * lq));
    }

    int buf = 0;
    for (int it = 0; it < 32; it++) {
#pragma unroll
        for (int l = 0; l < 2; l++) {
            const float* av = (const float*)&aR[l];
            const float* bv = (const float*)&bR[l];
#pragma unroll
            for (int i = 0; i < 4; i++) {
                As[buf][4 * lq + i][lr + 64 * l] = av[i];
                Bs[buf][4 * lq + i][lr + 64 * l] = bv[i];
            }
        }
        __syncthreads();

        if (it < 31) {
            const int k0 = (it + 1) * 16;
#pragma unroll
            for (int l = 0; l < 2; l++) {
                aR[l] = __ldg((const float4*)(X   + (size_t)(m0 + lr + 64 * l) * NI + k0 + 4 * lq));
                bR[l] = __ldg((const float4*)(Wih + (size_t)(n0 + lr + 64 * l) * NI + k0 + 4 * lq));
            }
        }

#pragma unroll
        for (int k = 0; k < 16; k++) {
            float4 a0 = *(const float4*)&As[buf][k][ty * 8];
            float4 a1 = *(const float4*)&As[buf][k][ty * 8 + 4];
            float4 b0 = *(const float4*)&Bs[buf][k][tx * 8];
            float4 b1 = *(const float4*)&Bs[buf][k][tx * 8 + 4];
            unsigned long long bb[4] = {pk2(b0.x, b0.y), pk2(b0.z, b0.w),
                                        pk2(b1.x, b1.y), pk2(b1.z, b1.w)};
            float av[8] = {a0.x, a0.y, a0.z, a0.w, a1.x, a1.y, a1.z, a1.w};
#pragma unroll
            for (int i = 0; i < 8; i++) {
                unsigned long long aa = pk2(av[i], av[i]);
#pragma unroll
                for (int j = 0; j < 4; j++) fma2(acc[i][j], aa, bb[j]);
            }
        }
        buf ^= 1;
        __syncthreads();
    }

    const int nb = n0 + tx * 8;
    float bias[8];
#pragma unroll
    for (int j = 0; j < 8; j++) bias[j] = __ldg(bih + nb + j) + __ldg(bhh + nb + j);

#pragma unroll
    for (int i = 0; i < 8; i++) {
        const int m = m0 + ty * 8 + i;
        const int t = m & (NT - 1);
        const int b = m >> 10;
        float* orow = g_xg + ((size_t)t * NB + b) * NG + nb;
#pragma unroll
        for (int j2 = 0; j2 < 4; j2++) {
            float2 v = upk(acc[i][j2]);
            v.x += bias[2 * j2];
            v.y += bias[2 * j2 + 1];
            *(float2*)(orow + 2 * j2) = v;
        }
    }
}

// ---------------- persistent scan kernel (v3: batch-grouped) ----------------
// 4 independent groups of 32 blocks; group gid owns batches [8*gid, 8*gid+8).
// Block r in group owns hidden units j0 = r*16..+15 (64 gate rows, W in smem).
// Per step: stage group's h (16KB) -> 16 warps: warp (c = w>>2, q = w&3)
// computes gate q's 16 rows x 8 batches over K-chunk c (128 k, k-packed f32x2),
// lane (rp, bp) register tile u in {rp, rp+8}, b in {bp, bp+4} -> sRed[4][512]
// -> 128-thread finalize (c-state in regs) -> publish h -> 32-block barrier.
__global__ void __launch_bounds__(SCAN_THREADS, 1) k_scan(float* __restrict__ out,
                                                          const float* __restrict__ Whh) {
    extern __shared__ float sm[];
    float* sW   = sm;                     // [64][WPAD]  gate-row slices
    float* sH   = sW + 64 * WPAD;         // [8][WPAD]   group hidden state
    float* sRed = sH + 8 * WPAD;          // [4][512]    K-chunk partials

    const int tid = threadIdx.x;
    const int bid = blockIdx.x;
    const int gid = bid >> 5;             // group
    const int r   = bid & 31;             // rank in group
    const int j0  = r * 16;

    // Load this block's 64 W_hh rows: sW row gl = q*16 + u  <- W_hh[q*512 + j0 + u][:]
    for (int idx = tid; idx < 64 * 512; idx += SCAN_THREADS) {
        const int gl = idx >> 9;
        const int k  = idx & 511;
        const int q  = gl >> 4;
        const int u  = gl & 15;
        sW[gl * WPAD + k] = __ldcg(Whh + (size_t)(q * 512 + j0 + u) * NH + k);
    }

    // dot-phase roles
    const int w    = tid >> 5;
    const int q    = w & 3;               // gate
    const int c    = w >> 2;              // K-chunk: k in [128c, 128c+128)
    const int lane = tid & 31;
    const int rp   = lane >> 2;           // unit: u in {rp, rp+8}
    const int bp   = lane & 3;            // batch: b in {bp, bp+4}

    // finalize roles (tid < 128): tid = fb*16 + u
    const int fu = tid & 15;
    const int fb = tid >> 4;

    unsigned mybar_tgt = 0;
    float creg = 0.0f;
    float xg[4];

    __syncthreads();   // sW ready

    // prefetch xg for t=0
    if (tid < 128) {
        const float* xrow = g_xg + ((size_t)0 * NB + gid * GBATCH + fb) * NG + j0 + fu;
#pragma unroll
        for (int qq = 0; qq < 4; qq++) xg[qq] = __ldcg(xrow + qq * 512);
    }

    for (int t = 0; t < NT; t++) {
        const int cur = t & 1;
        const int nxt = cur ^ 1;

        // ---- stage group's h (16KB) from L2 into smem ----
        {
            const float4* hp = (const float4*)&g_h[cur][gid][0][0];   // 1024 float4
#pragma unroll
            for (int i = 0; i < 2; i++) {
                const int f = tid + i * SCAN_THREADS;
                float4 v = __ldcg(hp + f);
                const int b  = f >> 7;
                const int k4 = (f & 127) * 4;
                *(float4*)&sH[b * WPAD + k4] = v;
            }
        }
        __syncthreads();

        // ---- dot phase (k-packed f32x2) ----
        unsigned long long acc00 = 0, acc01 = 0, acc10 = 0, acc11 = 0;
        {
            const ulonglong2* H0 = (const ulonglong2*)(sH + (size_t)bp * WPAD + 128 * c);
            const ulonglong2* H1 = (const ulonglong2*)(sH + (size_t)(bp + 4) * WPAD + 128 * c);
            const ulonglong2* W0 = (const ulonglong2*)(sW + (size_t)(q * 16 + rp) * WPAD + 128 * c);
            const ulonglong2* W1 = (const ulonglong2*)(sW + (size_t)(q * 16 + rp + 8) * WPAD + 128 * c);
#pragma unroll
            for (int kk = 0; kk < 32; kk++) {   // 4 k per iter
                const ulonglong2 h0 = H0[kk];
                const ulonglong2 h1 = H1[kk];
                const ulonglong2 w0 = W0[kk];
                const ulonglong2 w1 = W1[kk];
                fma2(acc00, h0.x, w0.x); fma2(acc00, h0.y, w0.y);
                fma2(acc01, h1.x, w0.x); fma2(acc01, h1.y, w0.y);
                fma2(acc10, h0.x, w1.x); fma2(acc10, h0.y, w1.y);
                fma2(acc11, h1.x, w1.x); fma2(acc11, h1.y, w1.y);
            }
        }
        // partial store: col = q*128 + b*16 + u
        {
            float2 p;
            p = upk(acc00); sRed[c * 512 + q * 128 + bp * 16 + rp]            = p.x + p.y;
            p = upk(acc10); sRed[c * 512 + q * 128 + bp * 16 + rp + 8]        = p.x + p.y;
            p = upk(acc01); sRed[c * 512 + q * 128 + (bp + 4) * 16 + rp]      = p.x + p.y;
            p = upk(acc11); sRed[c * 512 + q * 128 + (bp + 4) * 16 + rp + 8]  = p.x + p.y;
        }
        __syncthreads();

        // ---- finalize: sum 4 chunk partials, cell update, publish ----
        if (tid < 128) {
            float gate[4];
#pragma unroll
            for (int qq = 0; qq < 4; qq++) {
                gate[qq] = xg[qq]
                         + sRed[          qq * 128 + tid]
                         + sRed[1 * 512 + qq * 128 + tid]
                         + sRed[2 * 512 + qq * 128 + tid]
                         + sRed[3 * 512 + qq * 128 + tid];
            }
            const float ig = sigf(gate[0]);
            const float fg = sigf(gate[1]);
            const float gv = tanhfast(gate[2]);
            const float og = sigf(gate[3]);
            creg = fg * creg + ig * gv;
            const float hn = og * tanhfast(creg);

            const int j  = j0 + fu;
            const int bg = gid * GBATCH + fb;
            out[((size_t)bg * NT + t) * NH + j] = hn;
            __stcg(&g_h[nxt][gid][fb][j], hn);
            if (t == NT - 1) {
                out[(size_t)NB * NT * NH + (size_t)bg * NH + j] = hn;                       // h_T
                out[(size_t)NB * NT * NH + (size_t)NB * NH + (size_t)bg * NH + j] = creg;   // c_T
            }
            // prefetch next step's xg while others drain
            if (t + 1 < NT) {
                const float* xrow = g_xg + ((size_t)(t + 1) * NB + bg) * NG + j0 + fu;
#pragma unroll
                for (int qq = 0; qq < 4; qq++) xg[qq] = __ldcg(xrow + qq * 512);
            }
        }
        __syncthreads();

        // ---- group barrier (32 blocks, monotonic counter) ----
        if (tid == 0) {
            __threadfence();
            atomicAdd(&g_bars[gid * 32], 1u);
            mybar_tgt += GBLK;
            volatile unsigned* bp2 = &g_bars[gid * 32];
            while (*bp2 < mybar_tgt) { __nanosleep(20); }
            __threadfence();
        }
        __syncthreads();
    }
}

// ---------------- launch ----------------
extern "C" void kernel_launch(void* const* d_in, const int* in_sizes, int n_in,
                              void* d_out, int out_size) {
    const float* x    = (const float*)d_in[0];
    const float* Wih  = (const float*)d_in[1];
    const float* Whh  = (const float*)d_in[2];
    const float* bih  = (const float*)d_in[3];
    const float* bhh  = (const float*)d_in[4];
    float* out = (float*)d_out;

    const int scan_smem = (64 * WPAD + 8 * WPAD + 4 * 512) * (int)sizeof(float);  // 156,800 B
    cudaFuncSetAttribute(k_scan, cudaFuncAttributeMaxDynamicSharedMemorySize, scan_smem);

    k_init<<<16, 256>>>();

    dim3 ggrid(NG / 128, (NB * NT) / 128);   // (16, 256)
    k_gemm<<<ggrid, 256>>>(x, Wih, bih, bhh);

    k_scan<<<SCAN_BLOCKS, SCAN_THREADS, scan_smem>>>(out, Whh);
}

// round 10
// speedup vs baseline: 1.2881x; 1.2881x over previous
#include <cuda_runtime.h>
#include <cuda_bf16.h>
#include <cstdint>

// LSTM: B=32, T=1024, I=512, H=512, gates G=4H=2048
// out layout: outs[B][T][H] (16777216 floats) | h_T[B][H] | c_T[B][H]

#define NB 32
#define NT 1024
#define NI 512
#define NH 512
#define NG 2048

#define SCAN_BLOCKS 128
#define SCAN_THREADS 512

// ---------------- device scratch ----------------
__device__ float g_xg[(size_t)NT * NB * NG];      // [t][b][g]
__device__ float g_hT[2][NH * NB];                // transposed hidden [j][b], double-buffered
__device__ unsigned g_bar;                        // monotonic barrier counter
__device__ __nv_bfloat16 g_xh[(size_t)NB * NT * NI];   // x hi split
__device__ __nv_bfloat16 g_xl[(size_t)NB * NT * NI];   // x lo split
__device__ __nv_bfloat16 g_wh[(size_t)NG * NI];        // W_ih hi split
__device__ __nv_bfloat16 g_wl[(size_t)NG * NI];        // W_ih lo split

// ---------------- f32x2 helpers ----------------
__device__ __forceinline__ unsigned long long pk2(float lo, float hi) {
    unsigned long long r;
    asm("mov.b64 %0, {%1, %2};" : "=l"(r) : "f"(lo), "f"(hi));
    return r;
}
__device__ __forceinline__ void fma2(unsigned long long& acc,
                                     unsigned long long a, unsigned long long b) {
    asm("fma.rn.f32x2 %0, %1, %2, %0;" : "+l"(acc) : "l"(a), "l"(b));
}
__device__ __forceinline__ float2 upk(unsigned long long v) {
    float2 f;
    asm("mov.b64 {%0, %1}, %2;" : "=f"(f.x), "=f"(f.y) : "l"(v));
    return f;
}
__device__ __forceinline__ float sigf(float x) {
    return 1.0f / (1.0f + __expf(-x));
}

// ---------------- generic helpers ----------------
__device__ __forceinline__ uint32_t smem_u32(const void* p) {
    uint32_t a;
    asm("{ .reg .u64 t; cvta.to.shared.u64 t, %1; cvt.u32.u64 %0, t; }" : "=r"(a) : "l"(p));
    return a;
}
__device__ __forceinline__ uint32_t swz(uint32_t off) { return off ^ ((off >> 3) & 0x70); }

#define CP_ASYNC16(dst, src) \
    asm volatile("cp.async.cg.shared.global [%0], [%1], 16;" :: "r"(dst), "l"(src))
#define CP_COMMIT() asm volatile("cp.async.commit_group;" ::: "memory")

#define LDSM_X4(r0, r1, r2, r3, a) \
    asm volatile("ldmatrix.sync.aligned.m8n8.x4.shared.b16 {%0,%1,%2,%3}, [%4];" \
                 : "=r"(r0), "=r"(r1), "=r"(r2), "=r"(r3) : "r"(a))

#define MMA16816(c, a, b0, b1) \
    asm volatile("mma.sync.aligned.m16n8k16.row.col.f32.bf16.bf16.f32 " \
                 "{%0,%1,%2,%3}, {%4,%5,%6,%7}, {%8,%9}, {%0,%1,%2,%3};" \
                 : "+f"((c)[0]), "+f"((c)[1]), "+f"((c)[2]), "+f"((c)[3]) \
                 : "r"((a)[0]), "r"((a)[1]), "r"((a)[2]), "r"((a)[3]), \
                   "r"(b0), "r"(b1))

// ---------------- split + init kernel (runs every replay) ----------------
__global__ void __launch_bounds__(256) k_split(const float* __restrict__ X,
                                               const float* __restrict__ Wih) {
    const int gtid = threadIdx.x + blockIdx.x * blockDim.x;
    const int nthr = gridDim.x * blockDim.x;

    if (gtid == 0) g_bar = 0u;
    for (int i = gtid; i < 2 * NH * NB / 4; i += nthr)
        ((float4*)&g_hT[0][0])[i] = make_float4(0.f, 0.f, 0.f, 0.f);

    for (int i = gtid; i < NB * NT * NI / 4; i += nthr) {
        float4 v = __ldg((const float4*)X + i);
        const float* f = (const float*)&v;
        unsigned hi[2] = {0, 0}, lo[2] = {0, 0};
#pragma unroll
        for (int j = 0; j < 4; j++) {
            __nv_bfloat16 h = __float2bfloat16_rn(f[j]);
            __nv_bfloat16 l = __float2bfloat16_rn(f[j] - __bfloat162float(h));
            hi[j >> 1] |= (unsigned)__bfloat16_as_ushort(h) << ((j & 1) * 16);
            lo[j >> 1] |= (unsigned)__bfloat16_as_ushort(l) << ((j & 1) * 16);
        }
        ((uint2*)g_xh)[i] = make_uint2(hi[0], hi[1]);
        ((uint2*)g_xl)[i] = make_uint2(lo[0], lo[1]);
    }
    for (int i = gtid; i < NG * NI / 4; i += nthr) {
        float4 v = __ldg((const float4*)Wih + i);
        const float* f = (const float*)&v;
        unsigned hi[2] = {0, 0}, lo[2] = {0, 0};
#pragma unroll
        for (int j = 0; j < 4; j++) {
            __nv_bfloat16 h = __float2bfloat16_rn(f[j]);
            __nv_bfloat16 l = __float2bfloat16_rn(f[j] - __bfloat162float(h));
            hi[j >> 1] |= (unsigned)__bfloat16_as_ushort(h) << ((j & 1) * 16);
            lo[j >> 1] |= (unsigned)__bfloat16_as_ushort(l) << ((j & 1) * 16);
        }
        ((uint2*)g_wh)[i] = make_uint2(hi[0], hi[1]);
        ((uint2*)g_wl)[i] = make_uint2(lo[0], lo[1]);
    }
}

// ---------------- mma.sync GEMM ----------------
// xg[m][n] = X[m][:] . Wih[n][:] + bias[n], split as Ah*Bh + Al*Bh + Ah*Bl.
// Block: 128(m) x 128(n), 8 warps in 2(m) x 4(n): warp tile 64x32.
// K pipelined in 8 stages of 64; per stage 4 SW128 panels (Ah, Al, Bh, Bl;
// 128 rows x 128B) loaded via cp.async, 2-deep.
#define GHDR 1024
#define PANEL 16384
#define GBUF (4 * PANEL)

__device__ __forceinline__ void gemm_load_stage(uint32_t sb, uint32_t bufb, int kb,
                                                int tid, int m0, int n0) {
#pragma unroll
    for (int i = 0; i < 16; i++) {
        const int idx = tid + i * 256;
        const int panel = idx >> 10;
        const int row = (idx >> 3) & 127;
        const int sg = idx & 7;
        const __nv_bfloat16* src;
        if (panel == 0)      src = g_xh + (size_t)(m0 + row) * NI + kb + 8 * sg;
        else if (panel == 1) src = g_xl + (size_t)(m0 + row) * NI + kb + 8 * sg;
        else if (panel == 2) src = g_wh + (size_t)(n0 + row) * NI + kb + 8 * sg;
        else                 src = g_wl + (size_t)(n0 + row) * NI + kb + 8 * sg;
        CP_ASYNC16(sb + bufb + panel * PANEL + swz(row * 128 + sg * 16), src);
    }
}

__global__ void __launch_bounds__(256) k_gemm_mma(const float* __restrict__ bih,
                                                  const float* __restrict__ bhh) {
    extern __shared__ char smem[];
    const uint32_t sb = smem_u32(smem);
    const int tid = threadIdx.x;
    const int wid = tid >> 5;
    const int lane = tid & 31;
    const int n0 = blockIdx.x * 128;
    const int m0 = blockIdx.y * 128;
    float* sBias = (float*)smem;

    const int wm = wid & 1;       // m half (0-1)
    const int wn = wid >> 1;      // n quarter (0-3)

    if (tid < 128) sBias[tid] = __ldg(bih + n0 + tid) + __ldg(bhh + n0 + tid);

    // ldmatrix per-lane address precompute (swizzle XOR depends only on row)
    // A (x4, m16 x k16): lane -> row = wm*64 + mt*16 + (lane%16), colblk = lane/16
    uint32_t baseA[4], xorA[4];
#pragma unroll
    for (int mt = 0; mt < 4; mt++) {
        const int rA = wm * 64 + mt * 16 + (lane & 15);
        baseA[mt] = (uint32_t)rA * 128;
        xorA[mt] = (uint32_t)(rA & 7) << 4;
    }
    const uint32_t cA0 = (uint32_t)(lane >> 4) * 16;
    // B (x4, n16 x k16): lane group g = lane/8: row = wn*32 + pair*16 + (g>>1)*8 + lane%8,
    // k-col-block = (g&1)*8
    const int gB = lane >> 3;
    uint32_t baseB[2], xorB[2];
#pragma unroll
    for (int pr = 0; pr < 2; pr++) {
        const int rB = wn * 32 + pr * 16 + ((gB >> 1) << 3) + (lane & 7);
        baseB[pr] = (uint32_t)rB * 128;
        xorB[pr] = (uint32_t)(rB & 7) << 4;
    }
    const uint32_t cB0 = (uint32_t)(gB & 1) * 16;

    float acc[4][4][4];
#pragma unroll
    for (int mt = 0; mt < 4; mt++)
#pragma unroll
        for (int nt = 0; nt < 4; nt++)
#pragma unroll
            for (int e = 0; e < 4; e++) acc[mt][nt][e] = 0.0f;

    // prologue: stage 0
    gemm_load_stage(sb, GHDR, 0, tid, m0, n0);
    CP_COMMIT();

    for (int s = 0; s < 8; s++) {
        const uint32_t bufb = GHDR + (uint32_t)(s & 1) * GBUF;
        if (s < 7) {
            gemm_load_stage(sb, GHDR + (uint32_t)((s + 1) & 1) * GBUF, (s + 1) * 64, tid, m0, n0);
            CP_COMMIT();
            asm volatile("cp.async.wait_group 1;" ::: "memory");
        } else {
            asm volatile("cp.async.wait_group 0;" ::: "memory");
        }
        __syncthreads();

        const uint32_t pAh = sb + bufb + 0 * PANEL;
        const uint32_t pAl = sb + bufb + 1 * PANEL;
        const uint32_t pBh = sb + bufb + 2 * PANEL;
        const uint32_t pBl = sb + bufb + 3 * PANEL;

#pragma unroll
        for (int k16 = 0; k16 < 4; k16++) {
            const uint32_t cA = (uint32_t)k16 * 32 + cA0;
            const uint32_t cB = (uint32_t)k16 * 32 + cB0;

            uint32_t ah[4][4], al[4][4], bh[2][4], bl[2][4];
#pragma unroll
            for (int mt = 0; mt < 4; mt++) {
                LDSM_X4(ah[mt][0], ah[mt][1], ah[mt][2], ah[mt][3],
                        pAh + baseA[mt] + (cA ^ xorA[mt]));
                LDSM_X4(al[mt][0], al[mt][1], al[mt][2], al[mt][3],
                        pAl + baseA[mt] + (cA ^ xorA[mt]));
            }
#pragma unroll
            for (int pr = 0; pr < 2; pr++) {
                LDSM_X4(bh[pr][0], bh[pr][1], bh[pr][2], bh[pr][3],
                        pBh + baseB[pr] + (cB ^ xorB[pr]));
                LDSM_X4(bl[pr][0], bl[pr][1], bl[pr][2], bl[pr][3],
                        pBl + baseB[pr] + (cB ^ xorB[pr]));
            }
#pragma unroll
            for (int mt = 0; mt < 4; mt++)
#pragma unroll
                for (int nt = 0; nt < 4; nt++) {
                    const int pr = nt >> 1;
                    const int sub = nt & 1;
                    MMA16816(acc[mt][nt], ah[mt], bh[pr][sub * 2], bh[pr][sub * 2 + 1]);
                    MMA16816(acc[mt][nt], al[mt], bh[pr][sub * 2], bh[pr][sub * 2 + 1]);
                    MMA16816(acc[mt][nt], ah[mt], bl[pr][sub * 2], bl[pr][sub * 2 + 1]);
                }
        }
        __syncthreads();
    }

    // epilogue: C frag (m16n8): lane -> rows l/4 and l/4+8, cols 2*(l%4)+{0,1}
    const int b = m0 >> 10;
#pragma unroll
    for (int mt = 0; mt < 4; mt++) {
        const int mrow0 = m0 + wm * 64 + mt * 16 + (lane >> 2);
        const int t0 = mrow0 & (NT - 1);
        const int t1 = (mrow0 + 8) & (NT - 1);
        float* d0 = g_xg + ((size_t)t0 * NB + b) * NG + n0;
        float* d1 = g_xg + ((size_t)t1 * NB + b) * NG + n0;
#pragma unroll
        for (int nt = 0; nt < 4; nt++) {
            const int bn = wn * 32 + nt * 8 + 2 * (lane & 3);
            const float bz0 = sBias[bn], bz1 = sBias[bn + 1];
            *(float2*)(d0 + bn) = make_float2(acc[mt][nt][0] + bz0, acc[mt][nt][1] + bz1);
            *(float2*)(d1 + bn) = make_float2(acc[mt][nt][2] + bz0, acc[mt][nt][3] + bz1);
        }
    }
}

// ---------------- persistent scan kernel (v2, verbatim — best known) ----------------
__global__ void __launch_bounds__(SCAN_THREADS, 1) k_scan(float* __restrict__ out,
                                                          const float* __restrict__ Whh) {
    extern __shared__ float sm[];
    unsigned long long* sWT2 = (unsigned long long*)sm;       // [512][16] ull pairs (64 KB)
    float* sRed = (float*)(sWT2 + 512 * 16);                  // [16][512]
    float* sFin = sRed + 16 * 512;                            // [512]

    const int tid = threadIdx.x;
    const int bid = blockIdx.x;
    const int j0 = bid * 4;

    for (int idx = tid; idx < 16 * 512; idx += SCAN_THREADS) {
        const int gl = idx & 15;
        const int k  = idx >> 4;
        const int grow = (gl & 3) * 512 + j0 + (gl >> 2);
        const float wv = __ldg(Whh + (size_t)grow * NH + k);
        sWT2[(size_t)k * 16 + gl] = pk2(wv, wv);
    }

    const int w    = tid >> 5;
    const int lane = tid & 31;
    const int bg   = lane & 7;
    const int gg   = lane >> 3;

    const int fb  = tid & 31;
    const int fjj = tid >> 5;

    float creg = 0.0f;
    __syncthreads();

    for (int t = 0; t < NT; t++) {
        const int cur = t & 1;
        const int nxt = cur ^ 1;

        float xg[4];
        if (tid < 128) {
            const float* xrow = g_xg + ((size_t)t * NB + fb) * NG + j0 + fjj;
#pragma unroll
            for (int q = 0; q < 4; q++) xg[q] = __ldcg(xrow + q * 512);
        }

        unsigned long long acc[2][4];
#pragma unroll
        for (int bp = 0; bp < 2; bp++)
#pragma unroll
            for (int u = 0; u < 4; u++) acc[bp][u] = 0ull;

        const float* hk = g_hT[cur] + (w * 32) * NB + 4 * bg;

        ulonglong2 hb[2][8];
#pragma unroll
        for (int i = 0; i < 8; i++)
            hb[0][i] = __ldcg((const ulonglong2*)(hk + i * NB));

        int pb = 0;
#pragma unroll
        for (int gq = 0; gq < 4; gq++) {
            if (gq < 3) {
#pragma unroll
                for (int i = 0; i < 8; i++)
                    hb[pb ^ 1][i] = __ldcg((const ulonglong2*)(hk + (8 * (gq + 1) + i) * NB));
            }
#pragma unroll
            for (int i = 0; i < 8; i++) {
                const int k = 32 * w + 8 * gq + i;
                const ulonglong2* wp = (const ulonglong2*)(sWT2 + (size_t)k * 16 + 4 * gg);
                ulonglong2 w01 = wp[0];
                ulonglong2 w23 = wp[1];
                const unsigned long long hlo = hb[pb][i].x;
                const unsigned long long hhi = hb[pb][i].y;
                fma2(acc[0][0], hlo, w01.x);
                fma2(acc[0][1], hlo, w01.y);
                fma2(acc[0][2], hlo, w23.x);
                fma2(acc[0][3], hlo, w23.y);
                fma2(acc[1][0], hhi, w01.x);
                fma2(acc[1][1], hhi, w01.y);
                fma2(acc[1][2], hhi, w23.x);
                fma2(acc[1][3], hhi, w23.y);
            }
            pb ^= 1;
        }

#pragma unroll
        for (int bp = 0; bp < 2; bp++)
#pragma unroll
            for (int u = 0; u < 4; u++) {
                float2 p = upk(acc[bp][u]);
                sRed[w * 512 + (gg + 4 * bg + 32 * (2 * bp + 0) + 128 * u)] = p.x;
                sRed[w * 512 + (gg + 4 * bg + 32 * (2 * bp + 1) + 128 * u)] = p.y;
            }
        __syncthreads();

        {
            float s = sRed[tid];
#pragma unroll
            for (int r = 1; r < 16; r++) s += sRed[r * 512 + tid];
            sFin[tid] = s;
        }
        __syncthreads();

        if (tid < 128) {
            float gate[4];
#pragma unroll
            for (int q = 0; q < 4; q++) {
                const int c = fjj + 4 * (fb >> 2) + 32 * (fb & 3) + 128 * q;
                gate[q] = xg[q] + sFin[c];
            }
            const float ig = sigf(gate[0]);
            const float fg = sigf(gate[1]);
            const float gv = tanhf(gate[2]);
            const float og = sigf(gate[3]);
            creg = fg * creg + ig * gv;
            const float hn = og * tanhf(creg);

            const int j = j0 + fjj;
            out[((size_t)fb * NT + t) * NH + j] = hn;
            __stcg(&g_hT[nxt][j * NB + fb], hn);
            if (t == NT - 1) {
                out[(size_t)NB * NT * NH + fb * NH + j] = hn;
                out[(size_t)NB * NT * NH + NB * NH + fb * NH + j] = creg;
            }
        }
        __syncthreads();

        if (tid == 0) {
            __threadfence();
            atomicAdd(&g_bar, 1u);
            const unsigned target = (unsigned)SCAN_BLOCKS * (unsigned)(t + 1);
            volatile unsigned* bp2 = &g_bar;
            while (*bp2 < target) { __nanosleep(32); }
            __threadfence();
        }
        __syncthreads();
    }
}

// ---------------- launch ----------------
extern "C" void kernel_launch(void* const* d_in, const int* in_sizes, int n_in,
                              void* d_out, int out_size) {
    const float* x    = (const float*)d_in[0];
    const float* Wih  = (const float*)d_in[1];
    const float* Whh  = (const float*)d_in[2];
    const float* bih  = (const float*)d_in[3];
    const float* bhh  = (const float*)d_in[4];
    float* out = (float*)d_out;

    const int gemm_smem = GHDR + 2 * GBUF;   // 132,096 B
    cudaFuncSetAttribute(k_gemm_mma, cudaFuncAttributeMaxDynamicSharedMemorySize, gemm_smem);
    const int scan_smem = 512 * 16 * 8 + 16 * 512 * 4 + 512 * 4;  // 100,352 B
    cudaFuncSetAttribute(k_scan, cudaFuncAttributeMaxDynamicSharedMemorySize, scan_smem);

    k_split<<<1024, 256>>>(x, Wih);

    dim3 ggrid(NG / 128, (NB * NT) / 128);   // (16, 256)
    k_gemm_mma<<<ggrid, 256, gemm_smem>>>(bih, bhh);

    k_scan<<<SCAN_BLOCKS, SCAN_THREADS, scan_smem>>>(out, Whh);
}

// round 11
// speedup vs baseline: 1.6863x; 1.3092x over previous
#include <cuda_runtime.h>
#include <cuda_bf16.h>
#include <cstdint>

// LSTM: B=32, T=1024, I=512, H=512, gates G=4H=2048
// out layout: outs[B][T][H] (16777216 floats) | h_T[B][H] | c_T[B][H]

#define NB 32
#define NT 1024
#define NI 512
#define NH 512
#define NG 2048

#define SCAN_BLOCKS 128
#define SCAN_THREADS 512

// ---------------- device scratch ----------------
__device__ float g_xg[(size_t)NT * NB * NG];      // [t][b][g]
__device__ unsigned g_bar;                        // monotonic barrier counter
__device__ __nv_bfloat16 g_xh[(size_t)NB * NT * NI];   // x hi split
__device__ __nv_bfloat16 g_xl[(size_t)NB * NT * NI];   // x lo split
__device__ __nv_bfloat16 g_wh[(size_t)NG * NI];        // W_ih hi split
__device__ __nv_bfloat16 g_wl[(size_t)NG * NI];        // W_ih lo split
// hidden state as bf16 hi/lo, [b][j] contiguous j, double-buffered
__device__ unsigned short g_hh[2][NB * NH];
__device__ unsigned short g_hl[2][NB * NH];

__device__ __forceinline__ float sigf(float x) {
    return 1.0f / (1.0f + __expf(-x));
}
__device__ __forceinline__ uint32_t smem_u32(const void* p) {
    uint32_t a;
    asm("{ .reg .u64 t; cvta.to.shared.u64 t, %1; cvt.u32.u64 %0, t; }" : "=r"(a) : "l"(p));
    return a;
}
__device__ __forceinline__ uint32_t swz(uint32_t off) { return off ^ ((off >> 3) & 0x70); }

#define CP_ASYNC16(dst, src) \
    asm volatile("cp.async.cg.shared.global [%0], [%1], 16;" :: "r"(dst), "l"(src))
#define CP_COMMIT() asm volatile("cp.async.commit_group;" ::: "memory")

#define LDSM_X4(r0, r1, r2, r3, a) \
    asm volatile("ldmatrix.sync.aligned.m8n8.x4.shared.b16 {%0,%1,%2,%3}, [%4];" \
                 : "=r"(r0), "=r"(r1), "=r"(r2), "=r"(r3) : "r"(a))

#define MMA16816(c, a, b0, b1) \
    asm volatile("mma.sync.aligned.m16n8k16.row.col.f32.bf16.bf16.f32 " \
                 "{%0,%1,%2,%3}, {%4,%5,%6,%7}, {%8,%9}, {%0,%1,%2,%3};" \
                 : "+f"((c)[0]), "+f"((c)[1]), "+f"((c)[2]), "+f"((c)[3]) \
                 : "r"((a)[0]), "r"((a)[1]), "r"((a)[2]), "r"((a)[3]), \
                   "r"(b0), "r"(b1))

// ---------------- split + init kernel (runs every replay) ----------------
__global__ void __launch_bounds__(256) k_split(const float* __restrict__ X,
                                               const float* __restrict__ Wih) {
    const int gtid = threadIdx.x + blockIdx.x * blockDim.x;
    const int nthr = gridDim.x * blockDim.x;

    if (gtid == 0) g_bar = 0u;
    // zero h0 (bf16 0 == 0x0000)
    for (int i = gtid; i < NB * NH / 8; i += nthr) {
        ((uint4*)&g_hh[0][0])[i] = make_uint4(0, 0, 0, 0);
        ((uint4*)&g_hl[0][0])[i] = make_uint4(0, 0, 0, 0);
    }

    for (int i = gtid; i < NB * NT * NI / 4; i += nthr) {
        float4 v = __ldg((const float4*)X + i);
        const float* f = (const float*)&v;
        unsigned hi[2] = {0, 0}, lo[2] = {0, 0};
#pragma unroll
        for (int j = 0; j < 4; j++) {
            __nv_bfloat16 h = __float2bfloat16_rn(f[j]);
            __nv_bfloat16 l = __float2bfloat16_rn(f[j] - __bfloat162float(h));
            hi[j >> 1] |= (unsigned)__bfloat16_as_ushort(h) << ((j & 1) * 16);
            lo[j >> 1] |= (unsigned)__bfloat16_as_ushort(l) << ((j & 1) * 16);
        }
        ((uint2*)g_xh)[i] = make_uint2(hi[0], hi[1]);
        ((uint2*)g_xl)[i] = make_uint2(lo[0], lo[1]);
    }
    for (int i = gtid; i < NG * NI / 4; i += nthr) {
        float4 v = __ldg((const float4*)Wih + i);
        const float* f = (const float*)&v;
        unsigned hi[2] = {0, 0}, lo[2] = {0, 0};
#pragma unroll
        for (int j = 0; j < 4; j++) {
            __nv_bfloat16 h = __float2bfloat16_rn(f[j]);
            __nv_bfloat16 l = __float2bfloat16_rn(f[j] - __bfloat162float(h));
            hi[j >> 1] |= (unsigned)__bfloat16_as_ushort(h) << ((j & 1) * 16);
            lo[j >> 1] |= (unsigned)__bfloat16_as_ushort(l) << ((j & 1) * 16);
        }
        ((uint2*)g_wh)[i] = make_uint2(hi[0], hi[1]);
        ((uint2*)g_wl)[i] = make_uint2(lo[0], lo[1]);
    }
}

// ---------------- mma.sync GEMM (unchanged from round 10 — passing) ----------------
#define GHDR 1024
#define PANEL 16384
#define GBUF (4 * PANEL)

__device__ __forceinline__ void gemm_load_stage(uint32_t sb, uint32_t bufb, int kb,
                                                int tid, int m0, int n0) {
#pragma unroll
    for (int i = 0; i < 16; i++) {
        const int idx = tid + i * 256;
        const int panel = idx >> 10;
        const int row = (idx >> 3) & 127;
        const int sg = idx & 7;
        const __nv_bfloat16* src;
        if (panel == 0)      src = g_xh + (size_t)(m0 + row) * NI + kb + 8 * sg;
        else if (panel == 1) src = g_xl + (size_t)(m0 + row) * NI + kb + 8 * sg;
        else if (panel == 2) src = g_wh + (size_t)(n0 + row) * NI + kb + 8 * sg;
        else                 src = g_wl + (size_t)(n0 + row) * NI + kb + 8 * sg;
        CP_ASYNC16(sb + bufb + panel * PANEL + swz(row * 128 + sg * 16), src);
    }
}

__global__ void __launch_bounds__(256) k_gemm_mma(const float* __restrict__ bih,
                                                  const float* __restrict__ bhh) {
    extern __shared__ char smem[];
    const uint32_t sb = smem_u32(smem);
    const int tid = threadIdx.x;
    const int wid = tid >> 5;
    const int lane = tid & 31;
    const int n0 = blockIdx.x * 128;
    const int m0 = blockIdx.y * 128;
    float* sBias = (float*)smem;

    const int wm = wid & 1;
    const int wn = wid >> 1;

    if (tid < 128) sBias[tid] = __ldg(bih + n0 + tid) + __ldg(bhh + n0 + tid);

    uint32_t baseA[4], xorA[4];
#pragma unroll
    for (int mt = 0; mt < 4; mt++) {
        const int rA = wm * 64 + mt * 16 + (lane & 15);
        baseA[mt] = (uint32_t)rA * 128;
        xorA[mt] = (uint32_t)(rA & 7) << 4;
    }
    const uint32_t cA0 = (uint32_t)(lane >> 4) * 16;
    const int gB = lane >> 3;
    uint32_t baseB[2], xorB[2];
#pragma unroll
    for (int pr = 0; pr < 2; pr++) {
        const int rB = wn * 32 + pr * 16 + ((gB >> 1) << 3) + (lane & 7);
        baseB[pr] = (uint32_t)rB * 128;
        xorB[pr] = (uint32_t)(rB & 7) << 4;
    }
    const uint32_t cB0 = (uint32_t)(gB & 1) * 16;

    float acc[4][4][4];
#pragma unroll
    for (int mt = 0; mt < 4; mt++)
#pragma unroll
        for (int nt = 0; nt < 4; nt++)
#pragma unroll
            for (int e = 0; e < 4; e++) acc[mt][nt][e] = 0.0f;

    gemm_load_stage(sb, GHDR, 0, tid, m0, n0);
    CP_COMMIT();

    for (int s = 0; s < 8; s++) {
        const uint32_t bufb = GHDR + (uint32_t)(s & 1) * GBUF;
        if (s < 7) {
            gemm_load_stage(sb, GHDR + (uint32_t)((s + 1) & 1) * GBUF, (s + 1) * 64, tid, m0, n0);
            CP_COMMIT();
            asm volatile("cp.async.wait_group 1;" ::: "memory");
        } else {
            asm volatile("cp.async.wait_group 0;" ::: "memory");
        }
        __syncthreads();

        const uint32_t pAh = sb + bufb + 0 * PANEL;
        const uint32_t pAl = sb + bufb + 1 * PANEL;
        const uint32_t pBh = sb + bufb + 2 * PANEL;
        const uint32_t pBl = sb + bufb + 3 * PANEL;

#pragma unroll
        for (int k16 = 0; k16 < 4; k16++) {
            const uint32_t cA = (uint32_t)k16 * 32 + cA0;
            const uint32_t cB = (uint32_t)k16 * 32 + cB0;

            uint32_t ah[4][4], al[4][4], bh[2][4], bl[2][4];
#pragma unroll
            for (int mt = 0; mt < 4; mt++) {
                LDSM_X4(ah[mt][0], ah[mt][1], ah[mt][2], ah[mt][3],
                        pAh + baseA[mt] + (cA ^ xorA[mt]));
                LDSM_X4(al[mt][0], al[mt][1], al[mt][2], al[mt][3],
                        pAl + baseA[mt] + (cA ^ xorA[mt]));
            }
#pragma unroll
            for (int pr = 0; pr < 2; pr++) {
                LDSM_X4(bh[pr][0], bh[pr][1], bh[pr][2], bh[pr][3],
                        pBh + baseB[pr] + (cB ^ xorB[pr]));
                LDSM_X4(bl[pr][0], bl[pr][1], bl[pr][2], bl[pr][3],
                        pBl + baseB[pr] + (cB ^ xorB[pr]));
            }
#pragma unroll
            for (int mt = 0; mt < 4; mt++)
#pragma unroll
                for (int nt = 0; nt < 4; nt++) {
                    const int pr = nt >> 1;
                    const int sub = nt & 1;
                    MMA16816(acc[mt][nt], ah[mt], bh[pr][sub * 2], bh[pr][sub * 2 + 1]);
                    MMA16816(acc[mt][nt], al[mt], bh[pr][sub * 2], bh[pr][sub * 2 + 1]);
                    MMA16816(acc[mt][nt], ah[mt], bl[pr][sub * 2], bl[pr][sub * 2 + 1]);
                }
        }
        __syncthreads();
    }

    const int b = m0 >> 10;
#pragma unroll
    for (int mt = 0; mt < 4; mt++) {
        const int mrow0 = m0 + wm * 64 + mt * 16 + (lane >> 2);
        const int t0 = mrow0 & (NT - 1);
        const int t1 = (mrow0 + 8) & (NT - 1);
        float* d0 = g_xg + ((size_t)t0 * NB + b) * NG + n0;
        float* d1 = g_xg + ((size_t)t1 * NB + b) * NG + n0;
#pragma unroll
        for (int nt = 0; nt < 4; nt++) {
            const int bn = wn * 32 + nt * 8 + 2 * (lane & 3);
            const float bz0 = sBias[bn], bz1 = sBias[bn + 1];
            *(float2*)(d0 + bn) = make_float2(acc[mt][nt][0] + bz0, acc[mt][nt][1] + bz1);
            *(float2*)(d1 + bn) = make_float2(acc[mt][nt][2] + bz0, acc[mt][nt][3] + bz1);
        }
    }
}

// ---------------- persistent tensor-core scan ----------------
// 128 blocks x 512 threads (16 warps). Block owns j0=bid*4..+3 => 16 gate rows,
// A-tile m=16 (m = q*4+jj), K=512 split: warp w owns k in [32w, 32w+32) (2 k16).
// W_hh frags (hi/lo bf16) loaded into registers ONCE. Per step: stage h (bf16
// hi/lo, [b][k] rows of 1040B) -> 8 ldmatrix.x4 + 24 mma per warp -> sRed
// (scrambled cols, conflict-free) -> 512-thread reduce -> 128-thread finalize
// (c in regs) -> publish h hi/lo -> chip barrier.
#define HROW 1040                          // 520 bf16 per row (bank-shifted)
#define SOFF_HI 0
#define SOFF_LO (32 * HROW)                // 33280
#define SOFF_RED (2 * 32 * HROW)           // 66560 (floats; W staging aliases here)
#define SOFF_FIN (SOFF_RED + 16 * 512 * 4) // 99328
#define SCAN_SMEM (SOFF_FIN + 512 * 4)     // 101376

__device__ __forceinline__ int scol(int m, int b) {
    return m * 32 + ((b + 8 * (m & 3)) & 31);
}

__global__ void __launch_bounds__(SCAN_THREADS, 1) k_scan(float* __restrict__ out,
                                                          const float* __restrict__ Whh) {
    extern __shared__ char sm[];
    const uint32_t sb = smem_u32(sm);
    float* sRed = (float*)(sm + SOFF_RED);
    float* sFin = (float*)(sm + SOFF_FIN);

    const int tid = threadIdx.x;
    const int bid = blockIdx.x;
    const int j0 = bid * 4;
    const int wid = tid >> 5;
    const int lane = tid & 31;

    // ---- stage W_hh panel (hi/lo bf16, 16 rows x 512) into sRed region ----
    {
        char* sWh = sm + SOFF_RED;
        char* sWl = sm + SOFF_RED + 16 * HROW;
        for (int idx = tid; idx < 16 * 512; idx += SCAN_THREADS) {
            const int m = idx >> 9;
            const int k = idx & 511;
            const float wv = __ldg(Whh + (size_t)((m >> 2) * 512 + j0 + (m & 3)) * NH + k);
            const __nv_bfloat16 h = __float2bfloat16_rn(wv);
            const __nv_bfloat16 l = __float2bfloat16_rn(wv - __bfloat162float(h));
            *(unsigned short*)(sWh + m * HROW + 2 * k) = __bfloat16_as_ushort(h);
            *(unsigned short*)(sWl + m * HROW + 2 * k) = __bfloat16_as_ushort(l);
        }
    }
    __syncthreads();

    // ---- load W fragments (held in registers for the whole scan) ----
    const int k0 = wid * 32;
    uint32_t ah[2][4], al[2][4];
    {
        const uint32_t aRow = sb + SOFF_RED + (uint32_t)(lane & 15) * HROW
                            + (uint32_t)(lane >> 4) * 16;
#pragma unroll
        for (int ks = 0; ks < 2; ks++) {
            const uint32_t cofs = (uint32_t)(k0 + ks * 16) * 2;
            LDSM_X4(ah[ks][0], ah[ks][1], ah[ks][2], ah[ks][3], aRow + cofs);
            LDSM_X4(al[ks][0], al[ks][1], al[ks][2], al[ks][3],
                    aRow + 16 * HROW + cofs);
        }
    }
    __syncthreads();   // sRed region free for per-step reuse

    // B ldmatrix per-lane base: row = ((gB>>1)<<3)+(lane&7), k-half = (gB&1)*16B
    const int gB = lane >> 3;
    const uint32_t bBaseHi = sb + SOFF_HI
        + (uint32_t)(((gB >> 1) << 3) + (lane & 7)) * HROW + (uint32_t)(gB & 1) * 16;
    const uint32_t bBaseLo = bBaseHi + (SOFF_LO - SOFF_HI);

    // finalize roles (tid < 128): fb = tid>>2 (batch), fjj = tid&3 (unit)
    const int fb = tid >> 2;
    const int fjj = tid & 3;

    float creg = 0.0f;
    float xg[4];
    if (tid < 128) {
        const float* xrow = g_xg + ((size_t)fb) * NG + j0 + fjj;
#pragma unroll
        for (int q = 0; q < 4; q++) xg[q] = __ldcg(xrow + q * 512);
    }

    const int m0r = lane >> 2;          // c-frag row (and +8)
    const int bc0 = 2 * (lane & 3);     // c-frag col base within n8 tile

    for (int t = 0; t < NT; t++) {
        const int cur = t & 1;
        const int nxt = cur ^ 1;

        // ---- stage h hi/lo (32KB each) from L2 into smem [b][k] rows ----
        {
            const uint4* srcH = (const uint4*)&g_hh[cur][0];   // 2048 chunks
            const uint4* srcL = (const uint4*)&g_hl[cur][0];
#pragma unroll
            for (int i = 0; i < 4; i++) {
                const int f = tid + i * SCAN_THREADS;
                const int b = f >> 6;
                const int kc = f & 63;
                uint4 vh = __ldcg(srcH + f);
                uint4 vl = __ldcg(srcL + f);
                *(uint4*)(sm + SOFF_HI + b * HROW + kc * 16) = vh;
                *(uint4*)(sm + SOFF_LO + b * HROW + kc * 16) = vl;
            }
        }
        __syncthreads();

        // ---- tensor dot: 24 mma over this warp's K-chunk ----
        float acc[4][4];
#pragma unroll
        for (int nt = 0; nt < 4; nt++)
#pragma unroll
            for (int e = 0; e < 4; e++) acc[nt][e] = 0.0f;

#pragma unroll
        for (int ks = 0; ks < 2; ks++) {
            const uint32_t cofs = (uint32_t)(k0 + ks * 16) * 2;
            uint32_t bh[2][4], bl[2][4];
#pragma unroll
            for (int nn = 0; nn < 2; nn++) {
                LDSM_X4(bh[nn][0], bh[nn][1], bh[nn][2], bh[nn][3],
                        bBaseHi + (uint32_t)nn * 16 * HROW + cofs);
                LDSM_X4(bl[nn][0], bl[nn][1], bl[nn][2], bl[nn][3],
                        bBaseLo + (uint32_t)nn * 16 * HROW + cofs);
            }
#pragma unroll
            for (int nn = 0; nn < 2; nn++)
#pragma unroll
                for (int sub = 0; sub < 2; sub++) {
                    const int nt = nn * 2 + sub;
                    MMA16816(acc[nt], ah[ks], bh[nn][sub * 2], bh[nn][sub * 2 + 1]);
                    MMA16816(acc[nt], al[ks], bh[nn][sub * 2], bh[nn][sub * 2 + 1]);
                    MMA16816(acc[nt], ah[ks], bl[nn][sub * 2], bl[nn][sub * 2 + 1]);
                }
        }

        // ---- store partials (scrambled columns; STS.64 conflict-free) ----
#pragma unroll
        for (int nt = 0; nt < 4; nt++) {
            const int b0 = nt * 8 + bc0;
            *(float2*)&sRed[wid * 512 + scol(m0r, b0)]     = make_float2(acc[nt][0], acc[nt][1]);
            *(float2*)&sRed[wid * 512 + scol(m0r + 8, b0)] = make_float2(acc[nt][2], acc[nt][3]);
        }
        __syncthreads();

        // ---- pre-reduce over 16 K-chunks ----
        {
            float s = sRed[tid];
#pragma unroll
            for (int r = 1; r < 16; r++) s += sRed[r * 512 + tid];
            sFin[tid] = s;
        }
        __syncthreads();

        // ---- finalize ----
        if (tid < 128) {
            float gate[4];
#pragma unroll
            for (int q = 0; q < 4; q++) {
                const int m = q * 4 + fjj;
                gate[q] = xg[q] + sFin[m * 32 + ((fb + 8 * fjj) & 31)];
            }
            const float ig = sigf(gate[0]);
            const float fg = sigf(gate[1]);
            const float gv = tanhf(gate[2]);
            const float og = sigf(gate[3]);
            creg = fg * creg + ig * gv;
            const float hn = og * tanhf(creg);

            const int j = j0 + fjj;
            out[((size_t)fb * NT + t) * NH + j] = hn;

            const __nv_bfloat16 hh = __float2bfloat16_rn(hn);
            const __nv_bfloat16 hl = __float2bfloat16_rn(hn - __bfloat162float(hh));
            g_hh[nxt][fb * NH + j] = __bfloat16_as_ushort(hh);
            g_hl[nxt][fb * NH + j] = __bfloat16_as_ushort(hl);

            if (t == NT - 1) {
                out[(size_t)NB * NT * NH + (size_t)fb * NH + j] = hn;
                out[(size_t)NB * NT * NH + (size_t)NB * NH + (size_t)fb * NH + j] = creg;
            }
            if (t + 1 < NT) {
                const float* xrow = g_xg + ((size_t)(t + 1) * NB + fb) * NG + j0 + fjj;
#pragma unroll
                for (int q = 0; q < 4; q++) xg[q] = __ldcg(xrow + q * 512);
            }
        }
        __syncthreads();

        // ---- chip-wide barrier (monotonic counter) ----
        if (tid == 0) {
            __threadfence();
            atomicAdd(&g_bar, 1u);
            const unsigned target = (unsigned)SCAN_BLOCKS * (unsigned)(t + 1);
            volatile unsigned* bp2 = &g_bar;
            while (*bp2 < target) { __nanosleep(32); }
            __threadfence();
        }
        __syncthreads();
    }
}

// ---------------- launch ----------------
extern "C" void kernel_launch(void* const* d_in, const int* in_sizes, int n_in,
                              void* d_out, int out_size) {
    const float* x    = (const float*)d_in[0];
    const float* Wih  = (const float*)d_in[1];
    const float* Whh  = (const float*)d_in[2];
    const float* bih  = (const float*)d_in[3];
    const float* bhh  = (const float*)d_in[4];
    float* out = (float*)d_out;

    const int gemm_smem = GHDR + 2 * GBUF;   // 132,096 B
    cudaFuncSetAttribute(k_gemm_mma, cudaFuncAttributeMaxDynamicSharedMemorySize, gemm_smem);
    cudaFuncSetAttribute(k_scan, cudaFuncAttributeMaxDynamicSharedMemorySize, SCAN_SMEM);

    k_split<<<1024, 256>>>(x, Wih);

    dim3 ggrid(NG / 128, (NB * NT) / 128);   // (16, 256)
    k_gemm_mma<<<ggrid, 256, gemm_smem>>>(bih, bhh);

    k_scan<<<SCAN_BLOCKS, SCAN_THREADS, SCAN_SMEM>>>(out, Whh);
}